// round 15
// baseline (speedup 1.0000x reference)
#include <cuda_runtime.h>
#include <math.h>
#include <stdint.h>

// Problem constants
#define BQ    2        // batch
#define CC    128      // channels (Ci)
#define NSP   32768    // spatial d = 32*32*32
#define LSEQ  128      // language length
#define CTX   768      // language channels (Ct)
#define NHEAD 4
#define HDIM  32       // head dim
#define NBLK  256      // spatial blocks (NSP/128)
#define KVS   12       // kv split-K factor (768/64)
#define GEMMB (NBLK*BQ)            // 512 gemm blocks
#define KVPB  ((CC*BQ*KVS)/2)      // 1536 fused kv-partial blocks (2 sub-blocks each)
#define KVRB  ((CC*BQ)/2)          // 128 fused kv-reduce blocks

// ---------------- scratch (device globals: allocation-free) ----------------
__device__ float g_q   [BQ*CC*NSP];   // q pre-norm; REUSED as chain O-scratch after attention
__device__ float g_skip[BQ*CC*NSP];
__device__ float g_x   [BQ*CC*NSP];   // attention out, [b][n][ci] flat == weight_in flat
__device__ float g_w   [BQ*CC*NSP];
__device__ float g_k   [BQ*CC*LSEQ];
__device__ float g_v   [BQ*CC*LSEQ];
__device__ float g_kp  [BQ*KVS*CC*LSEQ];   // kv split-K partials
__device__ float g_vp  [BQ*KVS*CC*LSEQ];
__device__ float g_mu  [3*BQ*CC];     // slot0=q, slot1=skip, slot2=weight
__device__ float g_rs  [3*BQ*CC];
__device__ float g_ps  [3*BQ*CC*NBLK];   // per-block partial sums
__device__ float g_pq2 [3*BQ*CC*NBLK];   // per-block partial sumsq

__device__ __forceinline__ uint32_t f2tf32(float f) {
    uint32_t r;
    asm("cvt.rna.tf32.f32 %0, %1;" : "=r"(r) : "f"(f));
    return r;
}

__device__ __forceinline__ void mma_tf32(float c[4], const uint32_t a[4], const uint32_t b[2]) {
    asm volatile(
        "mma.sync.aligned.m16n8k8.row.col.f32.tf32.tf32.f32 "
        "{%0,%1,%2,%3}, {%4,%5,%6,%7}, {%8,%9}, {%0,%1,%2,%3};"
        : "+f"(c[0]), "+f"(c[1]), "+f"(c[2]), "+f"(c[3])
        : "r"(a[0]), "r"(a[1]), "r"(a[2]), "r"(a[3]), "r"(b[0]), "r"(b[1]));
}

#define SPAD 136   // row pitch in 32-bit words; 136%32==8 -> conflict-free fragment gathers

// stage one 32-K chunk of weights (row-major [o][c]) transposed into sW[k][o]
__device__ __forceinline__ void stage_w(uint32_t* sW, const float* __restrict__ W, int k0, int tid) {
    int o  = tid >> 1;
    int qh = tid & 1;
    const float4* wp = reinterpret_cast<const float4*>(W + o*CC + k0);
#pragma unroll
    for (int j = 0; j < 4; j++) {
        int kq = qh*4 + j;
        float4 w4 = wp[kq];
        int kk = kq*4;
        sW[(kk+0)*SPAD + o] = f2tf32(w4.x);
        sW[(kk+1)*SPAD + o] = f2tf32(w4.y);
        sW[(kk+2)*SPAD + o] = f2tf32(w4.z);
        sW[(kk+3)*SPAD + o] = f2tf32(w4.w);
    }
}

// ---------------- shared producer GEMM body ----------
struct GemmSmem {
    uint32_t sW[32*SPAD];
    uint32_t sX[32*SPAD];
    float redS[CC][4];
    float redQ[CC][4];
};

__device__ __forceinline__ void gemm_body(
    GemmSmem* sm, int bx, int by,
    const float* __restrict__ X,
    const float* __restrict__ W, const float* __restrict__ bias,
    float* __restrict__ out, float* __restrict__ ps, float* __restrict__ pq)
{
    uint32_t* sW = sm->sW;
    uint32_t* sX = sm->sX;
    const int b   = by;
    const int n0  = bx * 128;
    const int tid = threadIdx.x;
    const int lane = tid & 31;
    const int wid  = tid >> 5;
    const int wm = (wid >> 2) * 64;
    const int wn = (wid & 3) * 32;
    const size_t xbase = (size_t)b * CC * NSP;

    float acc[4][4][4];
#pragma unroll
    for (int mi = 0; mi < 4; mi++)
#pragma unroll
        for (int ni = 0; ni < 4; ni++)
#pragma unroll
            for (int r = 0; r < 4; r++) acc[mi][ni][r] = 0.f;

    for (int k0 = 0; k0 < CC; k0 += 32) {
        stage_w(sW, W, k0, tid);
        {
            int n4  = (tid & 31) * 4;
            int kkb = tid >> 5;
#pragma unroll
            for (int r = 0; r < 4; r++) {
                int kk = kkb + 8*r;
                size_t gi = xbase + (size_t)(k0+kk)*NSP + n0 + n4;
                float4 v = *reinterpret_cast<const float4*>(X + gi);
                uint4 u = make_uint4(f2tf32(v.x), f2tf32(v.y), f2tf32(v.z), f2tf32(v.w));
                *reinterpret_cast<uint4*>(&sX[kk*SPAD + n4]) = u;
            }
        }
        __syncthreads();
#pragma unroll
        for (int k8 = 0; k8 < 32; k8 += 8) {
            uint32_t af[4][4], bf[4][2];
#pragma unroll
            for (int mi = 0; mi < 4; mi++) {
                int o = wm + mi*16 + (lane >> 2);
                int k = k8 + (lane & 3);
                af[mi][0] = sW[k*SPAD + o];
                af[mi][1] = sW[k*SPAD + o+8];
                af[mi][2] = sW[(k+4)*SPAD + o];
                af[mi][3] = sW[(k+4)*SPAD + o+8];
            }
#pragma unroll
            for (int ni = 0; ni < 4; ni++) {
                int n = wn + ni*8 + (lane >> 2);
                int k = k8 + (lane & 3);
                bf[ni][0] = sX[k*SPAD + n];
                bf[ni][1] = sX[(k+4)*SPAD + n];
            }
#pragma unroll
            for (int mi = 0; mi < 4; mi++)
#pragma unroll
                for (int ni = 0; ni < 4; ni++)
                    mma_tf32(acc[mi][ni], af[mi], bf[ni]);
        }
        __syncthreads();
    }

    // epilogue + stats partials
    float sL[4], qL[4], sH[4], qH[4];
#pragma unroll
    for (int mi = 0; mi < 4; mi++) { sL[mi]=0.f; qL[mi]=0.f; sH[mi]=0.f; qH[mi]=0.f; }
#pragma unroll
    for (int mi = 0; mi < 4; mi++) {
        int o  = wm + mi*16 + (lane >> 2);
        float bi0 = bias[o];
        float bi1 = bias[o+8];
#pragma unroll
        for (int ni = 0; ni < 4; ni++) {
            int n = n0 + wn + ni*8 + (lane & 3)*2;
            size_t i0 = xbase + (size_t)o*NSP + n;
            size_t i1 = i0 + (size_t)8*NSP;
            float v0 = acc[mi][ni][0] + bi0;
            float v1 = acc[mi][ni][1] + bi0;
            float v2 = acc[mi][ni][2] + bi1;
            float v3 = acc[mi][ni][3] + bi1;
            sL[mi] += v0+v1; qL[mi] += v0*v0+v1*v1;
            sH[mi] += v2+v3; qH[mi] += v2*v2+v3*v3;
            *reinterpret_cast<float2*>(out + i0) = make_float2(v0, v1);
            *reinterpret_cast<float2*>(out + i1) = make_float2(v2, v3);
        }
    }
#pragma unroll
    for (int mi = 0; mi < 4; mi++) {
        sL[mi] += __shfl_xor_sync(0xffffffffu, sL[mi], 1);
        sL[mi] += __shfl_xor_sync(0xffffffffu, sL[mi], 2);
        qL[mi] += __shfl_xor_sync(0xffffffffu, qL[mi], 1);
        qL[mi] += __shfl_xor_sync(0xffffffffu, qL[mi], 2);
        sH[mi] += __shfl_xor_sync(0xffffffffu, sH[mi], 1);
        sH[mi] += __shfl_xor_sync(0xffffffffu, sH[mi], 2);
        qH[mi] += __shfl_xor_sync(0xffffffffu, qH[mi], 1);
        qH[mi] += __shfl_xor_sync(0xffffffffu, qH[mi], 2);
    }
    if ((lane & 3) == 0) {
        int col = wid & 3;
        int rg  = lane >> 2;
#pragma unroll
        for (int mi = 0; mi < 4; mi++) {
            int r = wm + mi*16 + rg;
            sm->redS[r][col] = sL[mi]; sm->redQ[r][col] = qL[mi];
            sm->redS[r+8][col] = sH[mi]; sm->redQ[r+8][col] = qH[mi];
        }
    }
    __syncthreads();
    if (tid < CC) {
        float s = sm->redS[tid][0]+sm->redS[tid][1]+sm->redS[tid][2]+sm->redS[tid][3];
        float q = sm->redQ[tid][0]+sm->redQ[tid][1]+sm->redQ[tid][2]+sm->redQ[tid][3];
        int bc = b*CC + tid;
        ps[bc*NBLK + bx] = s;
        pq[bc*NBLK + bx] = q;
    }
}

// ---------------- kv bodies ----------------
__device__ __forceinline__ void kvp_body(int kvsub, int l,
                                         const float* __restrict__ lang,
                                         const float* __restrict__ wk,
                                         const float* __restrict__ wv)
{
    int o    = kvsub & 127;
    int rest = kvsub >> 7;       // 0..23
    int b    = rest & 1;
    int ks   = rest >> 1;        // 0..11
    int c0   = ks * 64;
    const float* lp  = lang + ((size_t)b*CTX + c0)*LSEQ + l;
    const float* wkr = wk + (size_t)o*CTX + c0;
    const float* wvr = wv + (size_t)o*CTX + c0;
    float ka0=0.f, ka1=0.f, ka2=0.f, ka3=0.f;
    float va0=0.f, va1=0.f, va2=0.f, va3=0.f;
#pragma unroll 4
    for (int c = 0; c < 64; c += 4) {
        float x0 = lp[(size_t)(c+0)*LSEQ];
        float x1 = lp[(size_t)(c+1)*LSEQ];
        float x2 = lp[(size_t)(c+2)*LSEQ];
        float x3 = lp[(size_t)(c+3)*LSEQ];
        float4 wk4 = *reinterpret_cast<const float4*>(wkr + c);
        float4 wv4 = *reinterpret_cast<const float4*>(wvr + c);
        ka0 = fmaf(wk4.x, x0, ka0);
        ka1 = fmaf(wk4.y, x1, ka1);
        ka2 = fmaf(wk4.z, x2, ka2);
        ka3 = fmaf(wk4.w, x3, ka3);
        va0 = fmaf(wv4.x, x0, va0);
        va1 = fmaf(wv4.y, x1, va1);
        va2 = fmaf(wv4.z, x2, va2);
        va3 = fmaf(wv4.w, x3, va3);
    }
    size_t pi = (((size_t)b*KVS + ks)*CC + o)*LSEQ + l;
    g_kp[pi] = (ka0 + ka1) + (ka2 + ka3);
    g_vp[pi] = (va0 + va1) + (va2 + va3);
}

__device__ __forceinline__ void kvr_body(int kvsub, int l,
                                         const float* __restrict__ mask,
                                         const float* __restrict__ bk,
                                         const float* __restrict__ bv)
{
    int o = kvsub & 127;
    int b = kvsub >> 7;
    float ak = bk[o], av = bv[o];
#pragma unroll
    for (int ks = 0; ks < KVS; ks++) {
        size_t pi = (((size_t)b*KVS + ks)*CC + o)*LSEQ + l;
        ak += g_kp[pi];
        av += g_vp[pi];
    }
    float m = mask[b*LSEQ + l];
    g_k[((size_t)b*CC + o)*LSEQ + l] = ak * m;
    g_v[((size_t)b*CC + o)*LSEQ + l] = av * m;
}

// ---------------- fused launch 1: gemm(q) blocks + kv_partial blocks ----------------
__global__ __launch_bounds__(256, 2) void gemm_kvp_kernel(
    const float* __restrict__ X,
    const float* __restrict__ W, const float* __restrict__ bias,
    float* __restrict__ out, float* __restrict__ ps, float* __restrict__ pq,
    const float* __restrict__ lang, const float* __restrict__ wk, const float* __restrict__ wv)
{
    __shared__ GemmSmem sm;
    int bid = blockIdx.x;
    if (bid < GEMMB) {
        gemm_body(&sm, bid & 255, bid >> 8, X, W, bias, out, ps, pq);
    } else {
        int kvsub = (bid - GEMMB)*2 + (threadIdx.x >> 7);
        kvp_body(kvsub, threadIdx.x & 127, lang, wk, wv);
    }
}

// ---------------- fused launch 2: gemm(skip) blocks + kv_reduce blocks ----------------
__global__ __launch_bounds__(256, 2) void gemm_kvr_kernel(
    const float* __restrict__ X,
    const float* __restrict__ W, const float* __restrict__ bias,
    float* __restrict__ out, float* __restrict__ ps, float* __restrict__ pq,
    const float* __restrict__ mask, const float* __restrict__ bk, const float* __restrict__ bv)
{
    __shared__ GemmSmem sm;
    int bid = blockIdx.x;
    if (bid < GEMMB) {
        gemm_body(&sm, bid & 255, bid >> 8, X, W, bias, out, ps, pq);
    } else {
        int kvsub = (bid - GEMMB)*2 + (threadIdx.x >> 7);
        kvr_body(kvsub, threadIdx.x & 127, mask, bk, bv);
    }
}

// ---------------- standalone producer GEMM (wpw) ----------------
__global__ __launch_bounds__(256, 2) void gemm_tc(
    const float* __restrict__ X,
    const float* __restrict__ W, const float* __restrict__ bias,
    float* __restrict__ out, float* __restrict__ ps, float* __restrict__ pq)
{
    __shared__ GemmSmem sm;
    gemm_body(&sm, blockIdx.x, blockIdx.y, X, W, bias, out, ps, pq);
}

// ---------------- finalize stats ----------------
__global__ __launch_bounds__(256) void finalize_kernel(const float* __restrict__ ps,
                                                       const float* __restrict__ pq,
                                                       float* __restrict__ mu, float* __restrict__ rs)
{
    int e = blockIdx.x, t = threadIdx.x;
    float s = ps[e*NBLK + t];
    float q = pq[e*NBLK + t];
#pragma unroll
    for (int off = 16; off > 0; off >>= 1) {
        s += __shfl_down_sync(0xffffffffu, s, off);
        q += __shfl_down_sync(0xffffffffu, q, off);
    }
    __shared__ float sa[8], sb[8];
    int lane = t & 31, wid = t >> 5;
    if (lane == 0) { sa[wid] = s; sb[wid] = q; }
    __syncthreads();
    if (t == 0) {
        float ts = 0.f, tq = 0.f;
        for (int w = 0; w < 8; w++) { ts += sa[w]; tq += sb[w]; }
        float mean = ts * (1.f/NSP);
        float var  = tq * (1.f/NSP) - mean*mean;
        mu[e] = mean;
        rs[e] = rsqrtf(var + 1e-5f);
    }
}

// ---------------- pair-split flash attention: 2 threads per query, 16 channels each --------
// Halves per-thread registers (occ ~2x) and per-thread FMA issue; one shfl_xor(1)
// per score combines the two half-dot-products.
#define HHALF 16
__global__ __launch_bounds__(128) void attn_kernel(const float* __restrict__ qbuf,
                                                   const float* __restrict__ mask)
{
    __shared__ float ks[HDIM*LSEQ];
    __shared__ float vs[HDIM*LSEQ];
    __shared__ float qmu[HDIM];
    __shared__ float qrs[HDIM];
    __shared__ float mb[LSEQ];
    int bh = blockIdx.y;
    int b = bh >> 2, h = bh & 3;
    int n0 = blockIdx.x * 64;
    int t = threadIdx.x;
    int bch = b*CC + h*HDIM;

    for (int i = t; i < HDIM*LSEQ; i += 128) {
        int idx = (bch + (i >> 7))*LSEQ + (i & 127);
        ks[i] = g_k[idx];
        vs[i] = g_v[idx];
    }
    if (t < HDIM) {
        qmu[t] = g_mu[bch + t];
        qrs[t] = g_rs[bch + t] * 0.17677669529663687f;   // fold hd^-0.5
    }
    mb[t] = 10000.f * mask[b*LSEQ + t] - 10000.f;
    __syncthreads();

    int qi   = t >> 1;         // query within block (pair lanes 2q, 2q+1 share a query)
    int half = t & 1;          // channel half
    int n  = n0 + qi;
    int c0 = half * HHALF;

    float qv[HHALF];
#pragma unroll
    for (int c = 0; c < HHALF; c++)
        qv[c] = (qbuf[(size_t)(bch + c0 + c)*NSP + n] - qmu[c0 + c]) * qrs[c0 + c];

    float mx = -1e30f, ssum = 0.f;
    float xa[HHALF];
#pragma unroll
    for (int c = 0; c < HHALF; c++) xa[c] = 0.f;

    for (int l0 = 0; l0 < LSEQ; l0 += 16) {
        // ---- partial scores over this thread's 16 channels ----
        float s[16];
#pragma unroll
        for (int j0 = 0; j0 < 16; j0 += 4) {
            float s0 = 0.f, s1 = 0.f, s2 = 0.f, s3 = 0.f;
#pragma unroll
            for (int c = 0; c < HHALF; c++) {
                float4 k4 = *reinterpret_cast<const float4*>(&ks[(c0 + c)*LSEQ + l0 + j0]);
                float q = qv[c];
                s0 = fmaf(q, k4.x, s0); s1 = fmaf(q, k4.y, s1);
                s2 = fmaf(q, k4.z, s2); s3 = fmaf(q, k4.w, s3);
            }
            s[j0] = s0; s[j0+1] = s1; s[j0+2] = s2; s[j0+3] = s3;
        }
        // ---- combine halves + mask; both lanes end with identical full scores ----
        float cm = -1e30f;
#pragma unroll
        for (int j = 0; j < 16; j++) {
            s[j] += __shfl_xor_sync(0xffffffffu, s[j], 1);
            s[j] += mb[l0 + j];
            cm = fmaxf(cm, s[j]);
        }
        // ---- online softmax update (redundant in both lanes; identical values) ----
        float newm = fmaxf(mx, cm);
        float scale = __expf(mx - newm);
        ssum *= scale;
#pragma unroll
        for (int c = 0; c < HHALF; c++) xa[c] *= scale;
#pragma unroll
        for (int j = 0; j < 16; j++) {
            s[j] = __expf(s[j] - newm);
            ssum += s[j];
        }
        // ---- PV accumulate over this thread's 16 channels ----
#pragma unroll
        for (int c = 0; c < HHALF; c++) {
            float a = xa[c];
#pragma unroll
            for (int j = 0; j < 16; j += 4) {
                float4 v4 = *reinterpret_cast<const float4*>(&vs[(c0 + c)*LSEQ + l0 + j]);
                a = fmaf(s[j],   v4.x, a); a = fmaf(s[j+1], v4.y, a);
                a = fmaf(s[j+2], v4.z, a); a = fmaf(s[j+3], v4.w, a);
            }
            xa[c] = a;
        }
        mx = newm;
    }
    float inv = 1.f / ssum;

    float* op = g_x + ((size_t)b*NSP + n)*CC + h*HDIM + c0;
#pragma unroll
    for (int c = 0; c < HHALF; c += 4) {
        float4 v4 = make_float4(xa[c]*inv, xa[c+1]*inv, xa[c+2]*inv, xa[c+3]*inv);
        *reinterpret_cast<float4*>(op + c) = v4;
    }
}

// ---------------- fused chain: O-scratch in global (L2-resident), 2 CTAs/SM ----------------
__device__ __forceinline__ void chain_gemm(const float* __restrict__ Wg, uint32_t* sW,
                                           const uint32_t* sBb,
                                           float acc[4][4][4],
                                           int tid, int lane, int wm, int wn)
{
#pragma unroll
    for (int mi = 0; mi < 4; mi++)
#pragma unroll
        for (int ni = 0; ni < 4; ni++)
#pragma unroll
            for (int r = 0; r < 4; r++) acc[mi][ni][r] = 0.f;
    for (int k0 = 0; k0 < CC; k0 += 32) {
        stage_w(sW, Wg, k0, tid);
        __syncthreads();
#pragma unroll
        for (int k8 = 0; k8 < 32; k8 += 8) {
            uint32_t af[4][4], bf[4][2];
#pragma unroll
            for (int mi = 0; mi < 4; mi++) {
                int o = wm + mi*16 + (lane >> 2);
                int k = k8 + (lane & 3);
                af[mi][0] = sW[k*SPAD + o];
                af[mi][1] = sW[k*SPAD + o+8];
                af[mi][2] = sW[(k+4)*SPAD + o];
                af[mi][3] = sW[(k+4)*SPAD + o+8];
            }
            int kg = k0 + k8 + (lane & 3);
#pragma unroll
            for (int ni = 0; ni < 4; ni++) {
                int n = wn + ni*8 + (lane >> 2);
                bf[ni][0] = sBb[kg*SPAD + n];
                bf[ni][1] = sBb[(kg+4)*SPAD + n];
            }
#pragma unroll
            for (int mi = 0; mi < 4; mi++)
#pragma unroll
                for (int ni = 0; ni < 4; ni++)
                    mma_tf32(acc[mi][ni], af[mi], bf[ni]);
        }
        __syncthreads();
    }
}

#define CHAIN_SMEM ((32 + 128)*SPAD*4)   // sW + sB = 87040 bytes -> 2 CTA/SM
__global__ __launch_bounds__(256, 2) void chain_kernel(
    const float* __restrict__ SKIP, const float* __restrict__ WB,
    const float* __restrict__ mu1, const float* __restrict__ rs1,
    const float* __restrict__ mu2, const float* __restrict__ rs2,
    const float* __restrict__ wpo, const float* __restrict__ bpo,
    const float* __restrict__ wg1, const float* __restrict__ bg1,
    const float* __restrict__ wg2, const float* __restrict__ bg2,
    float* __restrict__ Oscr, float* __restrict__ out)
{
    extern __shared__ char smraw[];
    uint32_t* sW = reinterpret_cast<uint32_t*>(smraw);                       // [32][136]
    uint32_t* sB = reinterpret_cast<uint32_t*>(smraw + 32*SPAD*4);           // [128][136] tf32

    const int b   = blockIdx.y;
    const int n0  = blockIdx.x * 128;
    const int tid = threadIdx.x;
    const int lane = tid & 31;
    const int wid  = tid >> 5;
    const int wm = (wid >> 2) * 64;
    const int wn = (wid & 3) * 32;
    const size_t xbase = (size_t)b * CC * NSP;

    // stage full-K input tile: sB = tf32(norm(SKIP)*norm(WB))
    {
        int n4  = (tid & 31) * 4;
        int kkb = tid >> 5;
#pragma unroll
        for (int r = 0; r < 16; r++) {
            int c = kkb + 8*r;
            size_t gi = xbase + (size_t)c*NSP + n0 + n4;
            int sc = b*CC + c;
            float m1 = mu1[sc], r1 = rs1[sc], m2 = mu2[sc], r2 = rs2[sc];
            float4 v  = *reinterpret_cast<const float4*>(SKIP + gi);
            float4 v2 = *reinterpret_cast<const float4*>(WB + gi);
            v.x = ((v.x - m1)*r1) * ((v2.x - m2)*r2);
            v.y = ((v.y - m1)*r1) * ((v2.y - m2)*r2);
            v.z = ((v.z - m1)*r1) * ((v2.z - m2)*r2);
            v.w = ((v.w - m1)*r1) * ((v2.w - m2)*r2);
            uint4 u = make_uint4(f2tf32(v.x), f2tf32(v.y), f2tf32(v.z), f2tf32(v.w));
            *reinterpret_cast<uint4*>(&sB[c*SPAD + n4]) = u;
        }
    }
    __syncthreads();

    float acc[4][4][4];

    // GEMM1: o1 = relu(wpo @ sB + bpo); fp32 -> Oscr (global, L2-hot), tf32 -> sB (in place)
    chain_gemm(wpo, sW, sB, acc, tid, lane, wm, wn);
#pragma unroll
    for (int mi = 0; mi < 4; mi++) {
        int o = wm + mi*16 + (lane >> 2);
        float bi0 = bpo[o], bi1 = bpo[o+8];
#pragma unroll
        for (int ni = 0; ni < 4; ni++) {
            int n = wn + ni*8 + (lane & 3)*2;
            float v0 = fmaxf(acc[mi][ni][0] + bi0, 0.f);
            float v1 = fmaxf(acc[mi][ni][1] + bi0, 0.f);
            float v2 = fmaxf(acc[mi][ni][2] + bi1, 0.f);
            float v3 = fmaxf(acc[mi][ni][3] + bi1, 0.f);
            size_t i0 = xbase + (size_t)o*NSP + n0 + n;
            size_t i1 = i0 + (size_t)8*NSP;
            *reinterpret_cast<float2*>(Oscr + i0) = make_float2(v0, v1);
            *reinterpret_cast<float2*>(Oscr + i1) = make_float2(v2, v3);
            sB[o*SPAD + n]       = f2tf32(v0);
            sB[o*SPAD + n+1]     = f2tf32(v1);
            sB[(o+8)*SPAD + n]   = f2tf32(v2);
            sB[(o+8)*SPAD + n+1] = f2tf32(v3);
        }
    }
    __syncthreads();

    // GEMM2: t = relu(wg1 @ sB + bg1) -> sB (in place)
    chain_gemm(wg1, sW, sB, acc, tid, lane, wm, wn);
#pragma unroll
    for (int mi = 0; mi < 4; mi++) {
        int o = wm + mi*16 + (lane >> 2);
        float bi0 = bg1[o], bi1 = bg1[o+8];
#pragma unroll
        for (int ni = 0; ni < 4; ni++) {
            int n = wn + ni*8 + (lane & 3)*2;
            sB[o*SPAD + n]       = f2tf32(fmaxf(acc[mi][ni][0] + bi0, 0.f));
            sB[o*SPAD + n+1]     = f2tf32(fmaxf(acc[mi][ni][1] + bi0, 0.f));
            sB[(o+8)*SPAD + n]   = f2tf32(fmaxf(acc[mi][ni][2] + bi1, 0.f));
            sB[(o+8)*SPAD + n+1] = f2tf32(fmaxf(acc[mi][ni][3] + bi1, 0.f));
        }
    }
    __syncthreads();

    // GEMM3: final = tanh(wg2 @ sB + bg2) * Oscr -> global out
    chain_gemm(wg2, sW, sB, acc, tid, lane, wm, wn);
#pragma unroll
    for (int mi = 0; mi < 4; mi++) {
        int o = wm + mi*16 + (lane >> 2);
        float bi0 = bg2[o], bi1 = bg2[o+8];
#pragma unroll
        for (int ni = 0; ni < 4; ni++) {
            int n = wn + ni*8 + (lane & 3)*2;
            size_t i0 = xbase + (size_t)o*NSP + n0 + n;
            size_t i1 = i0 + (size_t)8*NSP;
            float2 o0 = *reinterpret_cast<const float2*>(Oscr + i0);
            float2 o1 = *reinterpret_cast<const float2*>(Oscr + i1);
            float v0 = tanhf(acc[mi][ni][0] + bi0) * o0.x;
            float v1 = tanhf(acc[mi][ni][1] + bi0) * o0.y;
            float v2 = tanhf(acc[mi][ni][2] + bi1) * o1.x;
            float v3 = tanhf(acc[mi][ni][3] + bi1) * o1.y;
            *reinterpret_cast<float2*>(out + i0) = make_float2(v0, v1);
            *reinterpret_cast<float2*>(out + i1) = make_float2(v2, v3);
        }
    }
}

// ---------------- host orchestration ----------------
extern "C" void kernel_launch(void* const* d_in, const int* in_sizes, int n_in,
                              void* d_out, int out_size)
{
    const float* img  = (const float*)d_in[0];
    const float* lang = (const float*)d_in[1];
    const float* mask = (const float*)d_in[2];
    const float* wq   = (const float*)d_in[3];
    const float* bq   = (const float*)d_in[4];
    const float* wk   = (const float*)d_in[5];
    const float* bk   = (const float*)d_in[6];
    const float* wv   = (const float*)d_in[7];
    const float* bv   = (const float*)d_in[8];
    const float* wpw  = (const float*)d_in[9];
    const float* bpw  = (const float*)d_in[10];
    const float* wpi  = (const float*)d_in[11];
    const float* bpi  = (const float*)d_in[12];
    const float* wpo  = (const float*)d_in[13];
    const float* bpo  = (const float*)d_in[14];
    const float* wg1  = (const float*)d_in[15];
    const float* bg1  = (const float*)d_in[16];
    const float* wg2  = (const float*)d_in[17];
    const float* bg2  = (const float*)d_in[18];
    float* out = (float*)d_out;

    void *pq, *pskip, *px, *pw, *pmu, *prs, *pps, *ppq;
    cudaGetSymbolAddress(&pq,   g_q);
    cudaGetSymbolAddress(&pskip,g_skip);
    cudaGetSymbolAddress(&px,   g_x);
    cudaGetSymbolAddress(&pw,   g_w);
    cudaGetSymbolAddress(&pmu,  g_mu);
    cudaGetSymbolAddress(&prs,  g_rs);
    cudaGetSymbolAddress(&pps,  g_ps);
    cudaGetSymbolAddress(&ppq,  g_pq2);
    float* Q    = (float*)pq;
    float* SKIP = (float*)pskip;
    float* X    = (float*)px;
    float* WB   = (float*)pw;
    float* MU   = (float*)pmu;
    float* RS   = (float*)prs;
    float* PS   = (float*)pps;
    float* PQ   = (float*)ppq;

    cudaFuncSetAttribute(chain_kernel, cudaFuncAttributeMaxDynamicSharedMemorySize, CHAIN_SMEM);

    const int E = BQ*CC;   // entries per stats slot

    // launch 1: gemm(q) + kv_partial (independent work overlapped in one grid)
    gemm_kvp_kernel<<<GEMMB + KVPB, 256>>>(img, wq, bq, Q,
                                           PS + 0*E*NBLK, PQ + 0*E*NBLK,
                                           lang, wk, wv);
    // launch 2: gemm(skip) + kv_reduce (partials complete after launch 1)
    gemm_kvr_kernel<<<GEMMB + KVRB, 256>>>(img, wpi, bpi, SKIP,
                                           PS + 1*E*NBLK, PQ + 1*E*NBLK,
                                           mask, bk, bv);
    finalize_kernel<<<2*E,256>>>(PS, PQ, MU, RS);           // slots 0,1

    attn_kernel<<<dim3(NSP/64, BQ*NHEAD), 128>>>(Q, mask);

    gemm_tc<<<dim3(NBLK, BQ),256>>>(X, wpw, bpw, WB, PS + 2*E*NBLK, PQ + 2*E*NBLK);
    finalize_kernel<<<E,256>>>(PS + 2*E*NBLK, PQ + 2*E*NBLK, MU + 2*E, RS + 2*E);   // slot 2

    // Q buffer is dead after attn -> reuse as fp32 O-scratch for the chain
    chain_kernel<<<dim3(NBLK, BQ),256,CHAIN_SMEM>>>(SKIP, WB,
                                        MU + 1*E, RS + 1*E, MU + 2*E, RS + 2*E,
                                        wpo, bpo, wg1, bg1, wg2, bg2, Q, out);
}

// round 16
// speedup vs baseline: 1.3704x; 1.3704x over previous
#include <cuda_runtime.h>
#include <math.h>
#include <stdint.h>

// Problem constants
#define BQ    2        // batch
#define CC    128      // channels (Ci)
#define NSP   32768    // spatial d = 32*32*32
#define LSEQ  128      // language length
#define CTX   768      // language channels (Ct)
#define NHEAD 4
#define HDIM  32       // head dim
#define NBLK  256      // spatial blocks (NSP/128)
#define KVS   12       // kv split-K factor (768/64)
#define GEMMB (NBLK*BQ)            // 512 gemm blocks
#define KVPB  ((CC*BQ*KVS)/2)      // 1536 fused kv-partial blocks (2 sub-blocks each)

// ---------------- scratch (device globals: allocation-free) ----------------
__device__ float g_q   [BQ*CC*NSP];   // q pre-norm; REUSED as chain O-scratch after attention
__device__ float g_skip[BQ*CC*NSP];
__device__ float g_x   [BQ*CC*NSP];   // attention out, [b][n][ci] flat == weight_in flat
__device__ float g_w   [BQ*CC*NSP];
__device__ float g_k   [BQ*CC*LSEQ];
__device__ float g_v   [BQ*CC*LSEQ];
__device__ float g_kp  [BQ*KVS*CC*LSEQ];   // kv split-K partials
__device__ float g_vp  [BQ*KVS*CC*LSEQ];
__device__ float g_mu  [3*BQ*CC];     // slot0=q, slot1=skip, slot2=weight
__device__ float g_rs  [3*BQ*CC];
__device__ float g_ps  [3*BQ*CC*NBLK];   // per-block partial sums
__device__ float g_pq2 [3*BQ*CC*NBLK];   // per-block partial sumsq

__device__ __forceinline__ uint32_t f2tf32(float f) {
    uint32_t r;
    asm("cvt.rna.tf32.f32 %0, %1;" : "=r"(r) : "f"(f));
    return r;
}

__device__ __forceinline__ void mma_tf32(float c[4], const uint32_t a[4], const uint32_t b[2]) {
    asm volatile(
        "mma.sync.aligned.m16n8k8.row.col.f32.tf32.tf32.f32 "
        "{%0,%1,%2,%3}, {%4,%5,%6,%7}, {%8,%9}, {%0,%1,%2,%3};"
        : "+f"(c[0]), "+f"(c[1]), "+f"(c[2]), "+f"(c[3])
        : "r"(a[0]), "r"(a[1]), "r"(a[2]), "r"(a[3]), "r"(b[0]), "r"(b[1]));
}

#define SPAD 136   // row pitch in 32-bit words; 136%32==8 -> conflict-free fragment gathers

// stage one 32-K chunk of weights (row-major [o][c]) transposed into sW[k][o]
__device__ __forceinline__ void stage_w(uint32_t* sW, const float* __restrict__ W, int k0, int tid) {
    int o  = tid >> 1;
    int qh = tid & 1;
    const float4* wp = reinterpret_cast<const float4*>(W + o*CC + k0);
#pragma unroll
    for (int j = 0; j < 4; j++) {
        int kq = qh*4 + j;
        float4 w4 = wp[kq];
        int kk = kq*4;
        sW[(kk+0)*SPAD + o] = f2tf32(w4.x);
        sW[(kk+1)*SPAD + o] = f2tf32(w4.y);
        sW[(kk+2)*SPAD + o] = f2tf32(w4.z);
        sW[(kk+3)*SPAD + o] = f2tf32(w4.w);
    }
}

// ---------------- shared producer GEMM body ----------
struct GemmSmem {
    uint32_t sW[32*SPAD];
    uint32_t sX[32*SPAD];
    float redS[CC][4];
    float redQ[CC][4];
};

__device__ __forceinline__ void gemm_body(
    GemmSmem* sm, int bx, int by,
    const float* __restrict__ X,
    const float* __restrict__ W, const float* __restrict__ bias,
    float* __restrict__ out, float* __restrict__ ps, float* __restrict__ pq)
{
    uint32_t* sW = sm->sW;
    uint32_t* sX = sm->sX;
    const int b   = by;
    const int n0  = bx * 128;
    const int tid = threadIdx.x;
    const int lane = tid & 31;
    const int wid  = tid >> 5;
    const int wm = (wid >> 2) * 64;
    const int wn = (wid & 3) * 32;
    const size_t xbase = (size_t)b * CC * NSP;

    float acc[4][4][4];
#pragma unroll
    for (int mi = 0; mi < 4; mi++)
#pragma unroll
        for (int ni = 0; ni < 4; ni++)
#pragma unroll
            for (int r = 0; r < 4; r++) acc[mi][ni][r] = 0.f;

    for (int k0 = 0; k0 < CC; k0 += 32) {
        stage_w(sW, W, k0, tid);
        {
            int n4  = (tid & 31) * 4;
            int kkb = tid >> 5;
#pragma unroll
            for (int r = 0; r < 4; r++) {
                int kk = kkb + 8*r;
                size_t gi = xbase + (size_t)(k0+kk)*NSP + n0 + n4;
                float4 v = *reinterpret_cast<const float4*>(X + gi);
                uint4 u = make_uint4(f2tf32(v.x), f2tf32(v.y), f2tf32(v.z), f2tf32(v.w));
                *reinterpret_cast<uint4*>(&sX[kk*SPAD + n4]) = u;
            }
        }
        __syncthreads();
#pragma unroll
        for (int k8 = 0; k8 < 32; k8 += 8) {
            uint32_t af[4][4], bf[4][2];
#pragma unroll
            for (int mi = 0; mi < 4; mi++) {
                int o = wm + mi*16 + (lane >> 2);
                int k = k8 + (lane & 3);
                af[mi][0] = sW[k*SPAD + o];
                af[mi][1] = sW[k*SPAD + o+8];
                af[mi][2] = sW[(k+4)*SPAD + o];
                af[mi][3] = sW[(k+4)*SPAD + o+8];
            }
#pragma unroll
            for (int ni = 0; ni < 4; ni++) {
                int n = wn + ni*8 + (lane >> 2);
                int k = k8 + (lane & 3);
                bf[ni][0] = sX[k*SPAD + n];
                bf[ni][1] = sX[(k+4)*SPAD + n];
            }
#pragma unroll
            for (int mi = 0; mi < 4; mi++)
#pragma unroll
                for (int ni = 0; ni < 4; ni++)
                    mma_tf32(acc[mi][ni], af[mi], bf[ni]);
        }
        __syncthreads();
    }

    // epilogue + stats partials
    float sL[4], qL[4], sH[4], qH[4];
#pragma unroll
    for (int mi = 0; mi < 4; mi++) { sL[mi]=0.f; qL[mi]=0.f; sH[mi]=0.f; qH[mi]=0.f; }
#pragma unroll
    for (int mi = 0; mi < 4; mi++) {
        int o  = wm + mi*16 + (lane >> 2);
        float bi0 = bias[o];
        float bi1 = bias[o+8];
#pragma unroll
        for (int ni = 0; ni < 4; ni++) {
            int n = n0 + wn + ni*8 + (lane & 3)*2;
            size_t i0 = xbase + (size_t)o*NSP + n;
            size_t i1 = i0 + (size_t)8*NSP;
            float v0 = acc[mi][ni][0] + bi0;
            float v1 = acc[mi][ni][1] + bi0;
            float v2 = acc[mi][ni][2] + bi1;
            float v3 = acc[mi][ni][3] + bi1;
            sL[mi] += v0+v1; qL[mi] += v0*v0+v1*v1;
            sH[mi] += v2+v3; qH[mi] += v2*v2+v3*v3;
            *reinterpret_cast<float2*>(out + i0) = make_float2(v0, v1);
            *reinterpret_cast<float2*>(out + i1) = make_float2(v2, v3);
        }
    }
#pragma unroll
    for (int mi = 0; mi < 4; mi++) {
        sL[mi] += __shfl_xor_sync(0xffffffffu, sL[mi], 1);
        sL[mi] += __shfl_xor_sync(0xffffffffu, sL[mi], 2);
        qL[mi] += __shfl_xor_sync(0xffffffffu, qL[mi], 1);
        qL[mi] += __shfl_xor_sync(0xffffffffu, qL[mi], 2);
        sH[mi] += __shfl_xor_sync(0xffffffffu, sH[mi], 1);
        sH[mi] += __shfl_xor_sync(0xffffffffu, sH[mi], 2);
        qH[mi] += __shfl_xor_sync(0xffffffffu, qH[mi], 1);
        qH[mi] += __shfl_xor_sync(0xffffffffu, qH[mi], 2);
    }
    if ((lane & 3) == 0) {
        int col = wid & 3;
        int rg  = lane >> 2;
#pragma unroll
        for (int mi = 0; mi < 4; mi++) {
            int r = wm + mi*16 + rg;
            sm->redS[r][col] = sL[mi]; sm->redQ[r][col] = qL[mi];
            sm->redS[r+8][col] = sH[mi]; sm->redQ[r+8][col] = qH[mi];
        }
    }
    __syncthreads();
    if (tid < CC) {
        float s = sm->redS[tid][0]+sm->redS[tid][1]+sm->redS[tid][2]+sm->redS[tid][3];
        float q = sm->redQ[tid][0]+sm->redQ[tid][1]+sm->redQ[tid][2]+sm->redQ[tid][3];
        int bc = b*CC + tid;
        ps[bc*NBLK + bx] = s;
        pq[bc*NBLK + bx] = q;
    }
}

// ---------------- kv partial body ----------------
__device__ __forceinline__ void kvp_body(int kvsub, int l,
                                         const float* __restrict__ lang,
                                         const float* __restrict__ wk,
                                         const float* __restrict__ wv)
{
    int o    = kvsub & 127;
    int rest = kvsub >> 7;       // 0..23
    int b    = rest & 1;
    int ks   = rest >> 1;        // 0..11
    int c0   = ks * 64;
    const float* lp  = lang + ((size_t)b*CTX + c0)*LSEQ + l;
    const float* wkr = wk + (size_t)o*CTX + c0;
    const float* wvr = wv + (size_t)o*CTX + c0;
    float ka0=0.f, ka1=0.f, ka2=0.f, ka3=0.f;
    float va0=0.f, va1=0.f, va2=0.f, va3=0.f;
#pragma unroll 4
    for (int c = 0; c < 64; c += 4) {
        float x0 = lp[(size_t)(c+0)*LSEQ];
        float x1 = lp[(size_t)(c+1)*LSEQ];
        float x2 = lp[(size_t)(c+2)*LSEQ];
        float x3 = lp[(size_t)(c+3)*LSEQ];
        float4 wk4 = *reinterpret_cast<const float4*>(wkr + c);
        float4 wv4 = *reinterpret_cast<const float4*>(wvr + c);
        ka0 = fmaf(wk4.x, x0, ka0);
        ka1 = fmaf(wk4.y, x1, ka1);
        ka2 = fmaf(wk4.z, x2, ka2);
        ka3 = fmaf(wk4.w, x3, ka3);
        va0 = fmaf(wv4.x, x0, va0);
        va1 = fmaf(wv4.y, x1, va1);
        va2 = fmaf(wv4.z, x2, va2);
        va3 = fmaf(wv4.w, x3, va3);
    }
    size_t pi = (((size_t)b*KVS + ks)*CC + o)*LSEQ + l;
    g_kp[pi] = (ka0 + ka1) + (ka2 + ka3);
    g_vp[pi] = (va0 + va1) + (va2 + va3);
}

// ---------------- fused launch 1: gemm(q) blocks + kv_partial blocks ----------------
__global__ __launch_bounds__(256, 2) void gemm_kvp_kernel(
    const float* __restrict__ X,
    const float* __restrict__ W, const float* __restrict__ bias,
    float* __restrict__ out, float* __restrict__ ps, float* __restrict__ pq,
    const float* __restrict__ lang, const float* __restrict__ wk, const float* __restrict__ wv)
{
    __shared__ GemmSmem sm;
    int bid = blockIdx.x;
    if (bid < GEMMB) {
        gemm_body(&sm, bid & 255, bid >> 8, X, W, bias, out, ps, pq);
    } else {
        int kvsub = (bid - GEMMB)*2 + (threadIdx.x >> 7);
        kvp_body(kvsub, threadIdx.x & 127, lang, wk, wv);
    }
}

// ---------------- standalone kv_reduce ----------------
__global__ __launch_bounds__(128) void kv_reduce(const float* __restrict__ mask,
                                                 const float* __restrict__ bk,
                                                 const float* __restrict__ bv)
{
    int o = blockIdx.x;
    int b = blockIdx.y;
    int l = threadIdx.x;
    float ak = bk[o], av = bv[o];
#pragma unroll
    for (int ks = 0; ks < KVS; ks++) {
        size_t pi = (((size_t)b*KVS + ks)*CC + o)*LSEQ + l;
        ak += g_kp[pi];
        av += g_vp[pi];
    }
    float m = mask[b*LSEQ + l];
    g_k[((size_t)b*CC + o)*LSEQ + l] = ak * m;
    g_v[((size_t)b*CC + o)*LSEQ + l] = av * m;
}

// ---------------- standalone producer GEMM (skip on stream2, wpw on main) ----------------
__global__ __launch_bounds__(256, 2) void gemm_tc(
    const float* __restrict__ X,
    const float* __restrict__ W, const float* __restrict__ bias,
    float* __restrict__ out, float* __restrict__ ps, float* __restrict__ pq)
{
    __shared__ GemmSmem sm;
    gemm_body(&sm, blockIdx.x, blockIdx.y, X, W, bias, out, ps, pq);
}

// ---------------- finalize stats ----------------
__global__ __launch_bounds__(256) void finalize_kernel(const float* __restrict__ ps,
                                                       const float* __restrict__ pq,
                                                       float* __restrict__ mu, float* __restrict__ rs)
{
    int e = blockIdx.x, t = threadIdx.x;
    float s = ps[e*NBLK + t];
    float q = pq[e*NBLK + t];
#pragma unroll
    for (int off = 16; off > 0; off >>= 1) {
        s += __shfl_down_sync(0xffffffffu, s, off);
        q += __shfl_down_sync(0xffffffffu, q, off);
    }
    __shared__ float sa[8], sb[8];
    int lane = t & 31, wid = t >> 5;
    if (lane == 0) { sa[wid] = s; sb[wid] = q; }
    __syncthreads();
    if (t == 0) {
        float ts = 0.f, tq = 0.f;
        for (int w = 0; w < 8; w++) { ts += sa[w]; tq += sb[w]; }
        float mean = ts * (1.f/NSP);
        float var  = tq * (1.f/NSP) - mean*mean;
        mu[e] = mean;
        rs[e] = rsqrtf(var + 1e-5f);
    }
}

// ---------------- flash attention (exact R11 version, local optimum) ----------------
__global__ __launch_bounds__(128) void attn_kernel(const float* __restrict__ qbuf,
                                                   const float* __restrict__ mask)
{
    __shared__ float ks[HDIM*LSEQ];
    __shared__ float vs[HDIM*LSEQ];
    __shared__ float qmu[HDIM];
    __shared__ float qrs[HDIM];
    __shared__ float mb[LSEQ];
    int bh = blockIdx.y;
    int b = bh >> 2, h = bh & 3;
    int n0 = blockIdx.x * 128;
    int t = threadIdx.x;

    for (int i = t; i < HDIM*LSEQ; i += 128) {
        int idx = (b*CC + h*HDIM + (i >> 7))*LSEQ + (i & 127);
        ks[i] = g_k[idx];
        vs[i] = g_v[idx];
    }
    if (t < HDIM) {
        int ch = b*CC + h*HDIM + t;
        qmu[t] = g_mu[ch];
        qrs[t] = g_rs[ch] * 0.17677669529663687f;   // fold hd^-0.5
    }
    mb[t] = 10000.f * mask[b*LSEQ + t] - 10000.f;
    __syncthreads();

    int n = n0 + t;
    float qv[HDIM];
#pragma unroll
    for (int c = 0; c < HDIM; c++)
        qv[c] = (qbuf[(size_t)(b*CC + h*HDIM + c)*NSP + n] - qmu[c]) * qrs[c];

    float mx = -1e30f, ssum = 0.f;
    float xa[HDIM];
#pragma unroll
    for (int c = 0; c < HDIM; c++) xa[c] = 0.f;

    for (int l0 = 0; l0 < LSEQ; l0 += 16) {
        float s[16];
        float cm = -1e30f;
#pragma unroll
        for (int j0 = 0; j0 < 16; j0 += 4) {
            float4 m4 = *reinterpret_cast<const float4*>(&mb[l0 + j0]);
            float s0 = m4.x, s1 = m4.y, s2 = m4.z, s3 = m4.w;
#pragma unroll
            for (int c = 0; c < HDIM; c++) {
                float4 k4 = *reinterpret_cast<const float4*>(&ks[c*LSEQ + l0 + j0]);
                float q = qv[c];
                s0 = fmaf(q, k4.x, s0); s1 = fmaf(q, k4.y, s1);
                s2 = fmaf(q, k4.z, s2); s3 = fmaf(q, k4.w, s3);
            }
            s[j0] = s0; s[j0+1] = s1; s[j0+2] = s2; s[j0+3] = s3;
            cm = fmaxf(cm, fmaxf(fmaxf(s0, s1), fmaxf(s2, s3)));
        }
        float newm = fmaxf(mx, cm);
        float scale = __expf(mx - newm);
        ssum *= scale;
#pragma unroll
        for (int c = 0; c < HDIM; c++) xa[c] *= scale;
#pragma unroll
        for (int j = 0; j < 16; j++) {
            s[j] = __expf(s[j] - newm);
            ssum += s[j];
        }
#pragma unroll
        for (int c = 0; c < HDIM; c++) {
            float a = xa[c];
#pragma unroll
            for (int j = 0; j < 16; j += 4) {
                float4 v4 = *reinterpret_cast<const float4*>(&vs[c*LSEQ + l0 + j]);
                a = fmaf(s[j],   v4.x, a); a = fmaf(s[j+1], v4.y, a);
                a = fmaf(s[j+2], v4.z, a); a = fmaf(s[j+3], v4.w, a);
            }
            xa[c] = a;
        }
        mx = newm;
    }
    float inv = 1.f / ssum;

    float* op = g_x + ((size_t)b*NSP + n)*CC + h*HDIM;
#pragma unroll
    for (int c = 0; c < HDIM; c += 4) {
        float4 v4 = make_float4(xa[c]*inv, xa[c+1]*inv, xa[c+2]*inv, xa[c+3]*inv);
        *reinterpret_cast<float4*>(op + c) = v4;
    }
}

// ---------------- fused chain: O-scratch in global (L2-resident), 2 CTAs/SM ----------------
__device__ __forceinline__ void chain_gemm(const float* __restrict__ Wg, uint32_t* sW,
                                           const uint32_t* sBb,
                                           float acc[4][4][4],
                                           int tid, int lane, int wm, int wn)
{
#pragma unroll
    for (int mi = 0; mi < 4; mi++)
#pragma unroll
        for (int ni = 0; ni < 4; ni++)
#pragma unroll
            for (int r = 0; r < 4; r++) acc[mi][ni][r] = 0.f;
    for (int k0 = 0; k0 < CC; k0 += 32) {
        stage_w(sW, Wg, k0, tid);
        __syncthreads();
#pragma unroll
        for (int k8 = 0; k8 < 32; k8 += 8) {
            uint32_t af[4][4], bf[4][2];
#pragma unroll
            for (int mi = 0; mi < 4; mi++) {
                int o = wm + mi*16 + (lane >> 2);
                int k = k8 + (lane & 3);
                af[mi][0] = sW[k*SPAD + o];
                af[mi][1] = sW[k*SPAD + o+8];
                af[mi][2] = sW[(k+4)*SPAD + o];
                af[mi][3] = sW[(k+4)*SPAD + o+8];
            }
            int kg = k0 + k8 + (lane & 3);
#pragma unroll
            for (int ni = 0; ni < 4; ni++) {
                int n = wn + ni*8 + (lane >> 2);
                bf[ni][0] = sBb[kg*SPAD + n];
                bf[ni][1] = sBb[(kg+4)*SPAD + n];
            }
#pragma unroll
            for (int mi = 0; mi < 4; mi++)
#pragma unroll
                for (int ni = 0; ni < 4; ni++)
                    mma_tf32(acc[mi][ni], af[mi], bf[ni]);
        }
        __syncthreads();
    }
}

#define CHAIN_SMEM ((32 + 128)*SPAD*4)   // sW + sB = 87040 bytes -> 2 CTA/SM
__global__ __launch_bounds__(256, 2) void chain_kernel(
    const float* __restrict__ SKIP, const float* __restrict__ WB,
    const float* __restrict__ mu1, const float* __restrict__ rs1,
    const float* __restrict__ mu2, const float* __restrict__ rs2,
    const float* __restrict__ wpo, const float* __restrict__ bpo,
    const float* __restrict__ wg1, const float* __restrict__ bg1,
    const float* __restrict__ wg2, const float* __restrict__ bg2,
    float* __restrict__ Oscr, float* __restrict__ out)
{
    extern __shared__ char smraw[];
    uint32_t* sW = reinterpret_cast<uint32_t*>(smraw);                       // [32][136]
    uint32_t* sB = reinterpret_cast<uint32_t*>(smraw + 32*SPAD*4);           // [128][136] tf32

    const int b   = blockIdx.y;
    const int n0  = blockIdx.x * 128;
    const int tid = threadIdx.x;
    const int lane = tid & 31;
    const int wid  = tid >> 5;
    const int wm = (wid >> 2) * 64;
    const int wn = (wid & 3) * 32;
    const size_t xbase = (size_t)b * CC * NSP;

    // stage full-K input tile: sB = tf32(norm(SKIP)*norm(WB))
    {
        int n4  = (tid & 31) * 4;
        int kkb = tid >> 5;
#pragma unroll
        for (int r = 0; r < 16; r++) {
            int c = kkb + 8*r;
            size_t gi = xbase + (size_t)c*NSP + n0 + n4;
            int sc = b*CC + c;
            float m1 = mu1[sc], r1 = rs1[sc], m2 = mu2[sc], r2 = rs2[sc];
            float4 v  = *reinterpret_cast<const float4*>(SKIP + gi);
            float4 v2 = *reinterpret_cast<const float4*>(WB + gi);
            v.x = ((v.x - m1)*r1) * ((v2.x - m2)*r2);
            v.y = ((v.y - m1)*r1) * ((v2.y - m2)*r2);
            v.z = ((v.z - m1)*r1) * ((v2.z - m2)*r2);
            v.w = ((v.w - m1)*r1) * ((v2.w - m2)*r2);
            uint4 u = make_uint4(f2tf32(v.x), f2tf32(v.y), f2tf32(v.z), f2tf32(v.w));
            *reinterpret_cast<uint4*>(&sB[c*SPAD + n4]) = u;
        }
    }
    __syncthreads();

    float acc[4][4][4];

    // GEMM1: o1 = relu(wpo @ sB + bpo); fp32 -> Oscr (global, L2-hot), tf32 -> sB (in place)
    chain_gemm(wpo, sW, sB, acc, tid, lane, wm, wn);
#pragma unroll
    for (int mi = 0; mi < 4; mi++) {
        int o = wm + mi*16 + (lane >> 2);
        float bi0 = bpo[o], bi1 = bpo[o+8];
#pragma unroll
        for (int ni = 0; ni < 4; ni++) {
            int n = wn + ni*8 + (lane & 3)*2;
            float v0 = fmaxf(acc[mi][ni][0] + bi0, 0.f);
            float v1 = fmaxf(acc[mi][ni][1] + bi0, 0.f);
            float v2 = fmaxf(acc[mi][ni][2] + bi1, 0.f);
            float v3 = fmaxf(acc[mi][ni][3] + bi1, 0.f);
            size_t i0 = xbase + (size_t)o*NSP + n0 + n;
            size_t i1 = i0 + (size_t)8*NSP;
            *reinterpret_cast<float2*>(Oscr + i0) = make_float2(v0, v1);
            *reinterpret_cast<float2*>(Oscr + i1) = make_float2(v2, v3);
            sB[o*SPAD + n]       = f2tf32(v0);
            sB[o*SPAD + n+1]     = f2tf32(v1);
            sB[(o+8)*SPAD + n]   = f2tf32(v2);
            sB[(o+8)*SPAD + n+1] = f2tf32(v3);
        }
    }
    __syncthreads();

    // GEMM2: t = relu(wg1 @ sB + bg1) -> sB (in place)
    chain_gemm(wg1, sW, sB, acc, tid, lane, wm, wn);
#pragma unroll
    for (int mi = 0; mi < 4; mi++) {
        int o = wm + mi*16 + (lane >> 2);
        float bi0 = bg1[o], bi1 = bg1[o+8];
#pragma unroll
        for (int ni = 0; ni < 4; ni++) {
            int n = wn + ni*8 + (lane & 3)*2;
            sB[o*SPAD + n]       = f2tf32(fmaxf(acc[mi][ni][0] + bi0, 0.f));
            sB[o*SPAD + n+1]     = f2tf32(fmaxf(acc[mi][ni][1] + bi0, 0.f));
            sB[(o+8)*SPAD + n]   = f2tf32(fmaxf(acc[mi][ni][2] + bi1, 0.f));
            sB[(o+8)*SPAD + n+1] = f2tf32(fmaxf(acc[mi][ni][3] + bi1, 0.f));
        }
    }
    __syncthreads();

    // GEMM3: final = tanh(wg2 @ sB + bg2) * Oscr -> global out
    chain_gemm(wg2, sW, sB, acc, tid, lane, wm, wn);
#pragma unroll
    for (int mi = 0; mi < 4; mi++) {
        int o = wm + mi*16 + (lane >> 2);
        float bi0 = bg2[o], bi1 = bg2[o+8];
#pragma unroll
        for (int ni = 0; ni < 4; ni++) {
            int n = wn + ni*8 + (lane & 3)*2;
            size_t i0 = xbase + (size_t)o*NSP + n0 + n;
            size_t i1 = i0 + (size_t)8*NSP;
            float2 o0 = *reinterpret_cast<const float2*>(Oscr + i0);
            float2 o1 = *reinterpret_cast<const float2*>(Oscr + i1);
            float v0 = tanhf(acc[mi][ni][0] + bi0) * o0.x;
            float v1 = tanhf(acc[mi][ni][1] + bi0) * o0.y;
            float v2 = tanhf(acc[mi][ni][2] + bi1) * o1.x;
            float v3 = tanhf(acc[mi][ni][3] + bi1) * o1.y;
            *reinterpret_cast<float2*>(out + i0) = make_float2(v0, v1);
            *reinterpret_cast<float2*>(out + i1) = make_float2(v2, v3);
        }
    }
}

// ---------------- host orchestration (fork/join: skip-gemm overlaps attention) ----------
extern "C" void kernel_launch(void* const* d_in, const int* in_sizes, int n_in,
                              void* d_out, int out_size)
{
    const float* img  = (const float*)d_in[0];
    const float* lang = (const float*)d_in[1];
    const float* mask = (const float*)d_in[2];
    const float* wq   = (const float*)d_in[3];
    const float* bq   = (const float*)d_in[4];
    const float* wk   = (const float*)d_in[5];
    const float* bk   = (const float*)d_in[6];
    const float* wv   = (const float*)d_in[7];
    const float* bv   = (const float*)d_in[8];
    const float* wpw  = (const float*)d_in[9];
    const float* bpw  = (const float*)d_in[10];
    const float* wpi  = (const float*)d_in[11];
    const float* bpi  = (const float*)d_in[12];
    const float* wpo  = (const float*)d_in[13];
    const float* bpo  = (const float*)d_in[14];
    const float* wg1  = (const float*)d_in[15];
    const float* bg1  = (const float*)d_in[16];
    const float* wg2  = (const float*)d_in[17];
    const float* bg2  = (const float*)d_in[18];
    float* out = (float*)d_out;

    void *pq, *pskip, *px, *pw, *pmu, *prs, *pps, *ppq;
    cudaGetSymbolAddress(&pq,   g_q);
    cudaGetSymbolAddress(&pskip,g_skip);
    cudaGetSymbolAddress(&px,   g_x);
    cudaGetSymbolAddress(&pw,   g_w);
    cudaGetSymbolAddress(&pmu,  g_mu);
    cudaGetSymbolAddress(&prs,  g_rs);
    cudaGetSymbolAddress(&pps,  g_ps);
    cudaGetSymbolAddress(&ppq,  g_pq2);
    float* Q    = (float*)pq;
    float* SKIP = (float*)pskip;
    float* X    = (float*)px;
    float* WB   = (float*)pw;
    float* MU   = (float*)pmu;
    float* RS   = (float*)prs;
    float* PS   = (float*)pps;
    float* PQ   = (float*)ppq;

    cudaFuncSetAttribute(chain_kernel, cudaFuncAttributeMaxDynamicSharedMemorySize, CHAIN_SMEM);

    // one-time side-stream + events (host resources only; no device allocation)
    static cudaStream_t s2 = nullptr;
    static cudaEvent_t ev_fork = nullptr, ev_join = nullptr;
    if (s2 == nullptr) {
        cudaStreamCreateWithFlags(&s2, cudaStreamNonBlocking);
        cudaEventCreateWithFlags(&ev_fork, cudaEventDisableTiming);
        cudaEventCreateWithFlags(&ev_join, cudaEventDisableTiming);
    }

    const int E = BQ*CC;   // entries per stats slot
    dim3 gg(NBLK, BQ);

    // launch 1 (main): gemm(q) + kv_partial blocks
    gemm_kvp_kernel<<<GEMMB + KVPB, 256>>>(img, wq, bq, Q,
                                           PS + 0*E*NBLK, PQ + 0*E*NBLK,
                                           lang, wk, wv);

    // fork: skip-gemm + its finalize run on s2, overlapping kvr/finalize0/attn below
    cudaEventRecord(ev_fork, 0);
    cudaStreamWaitEvent(s2, ev_fork, 0);
    gemm_tc<<<gg, 256, 0, s2>>>(img, wpi, bpi, SKIP, PS + 1*E*NBLK, PQ + 1*E*NBLK);
    finalize_kernel<<<E, 256, 0, s2>>>(PS + 1*E*NBLK, PQ + 1*E*NBLK, MU + E, RS + E);
    cudaEventRecord(ev_join, s2);

    // main: kv reduce, q-stats, attention (low-occupancy; s2 gemm fills the SMs)
    kv_reduce<<<dim3(CC, BQ), 128>>>(mask, bk, bv);
    finalize_kernel<<<E, 256>>>(PS + 0*E*NBLK, PQ + 0*E*NBLK, MU, RS);
    attn_kernel<<<dim3(NBLK, BQ*NHEAD), 128>>>(Q, mask);

    // main: wpw gemm + stats (needs attention output only)
    gemm_tc<<<gg, 256>>>(X, wpw, bpw, WB, PS + 2*E*NBLK, PQ + 2*E*NBLK);
    finalize_kernel<<<E, 256>>>(PS + 2*E*NBLK, PQ + 2*E*NBLK, MU + 2*E, RS + 2*E);

    // join: chain needs SKIP + slot1 stats from s2
    cudaStreamWaitEvent(0, ev_join, 0);
    chain_kernel<<<gg, 256, CHAIN_SMEM>>>(SKIP, WB,
                                          MU + 1*E, RS + 1*E, MU + 2*E, RS + 2*E,
                                          wpo, bpo, wg1, bg1, wg2, bg2, Q, out);
}